// round 4
// baseline (speedup 1.0000x reference)
#include <cuda_runtime.h>

// EfficientGNN: 2-layer GCN + mean-over-nodes, algebraically collapsed.
// Node state interleaved as float4 A[i] = {p, dinv, u, v} so that each edge
// endpoint's gather+RED share one 32B L2 sector:
//   r: gather p[r] (+0)  & RED v[r] (+12)
//   c: gather dinv[c](+4)& RED u[c] (+8)
//   s[i] = dinv*(p+u),  w[i] = dinv*(dinv+v)
//   t[f] = sum_i w[i]*relu(s[i]*W1[f]+b1[f]);  out = t@W2 / N + b2

#define NMAX 100000
#define HID  128

__device__ float4 g_A[NMAX];               // {p, dinv, u, v}
__device__ float  g_deg_t[NMAX + HID];     // [0:N) deg accum, [N:N+HID) t  (one memset)

__global__ void k_deg(const int* __restrict__ col, int E) {
    float* deg = g_deg_t;
    int i = blockIdx.x * blockDim.x + threadIdx.x;
    int e0 = i * 4;
    if (e0 + 3 < E) {
        int4 c = *reinterpret_cast<const int4*>(col + e0);
        atomicAdd(&deg[c.x], 1.0f);
        atomicAdd(&deg[c.y], 1.0f);
        atomicAdd(&deg[c.z], 1.0f);
        atomicAdd(&deg[c.w], 1.0f);
    } else {
        for (int e = e0; e < E; ++e) atomicAdd(&deg[col[e]], 1.0f);
    }
}

__global__ void k_dinv(const float* __restrict__ x, int n) {
    int i = blockIdx.x * blockDim.x + threadIdx.x;
    if (i < n) {
        float d = rsqrtf(g_deg_t[i] + 1.0f);   // +1 self loop
        g_A[i] = make_float4(d * x[i], d, 0.0f, 0.0f);  // zeroes u,v too
    }
}

__global__ void k_edge(const int* __restrict__ row, const int* __restrict__ col, int E) {
    float* A = reinterpret_cast<float*>(g_A);
    int i = blockIdx.x * blockDim.x + threadIdx.x;
    int e0 = i * 4;
    if (e0 + 3 < E) {
        int4 r = *reinterpret_cast<const int4*>(row + e0);
        int4 c = *reinterpret_cast<const int4*>(col + e0);
        // gathers first (MLP), then REDs into the SAME sectors
        float p0 = A[4*r.x + 0], p1 = A[4*r.y + 0], p2 = A[4*r.z + 0], p3 = A[4*r.w + 0];
        float d0 = A[4*c.x + 1], d1 = A[4*c.y + 1], d2 = A[4*c.z + 1], d3 = A[4*c.w + 1];
        atomicAdd(&A[4*c.x + 2], p0);
        atomicAdd(&A[4*c.y + 2], p1);
        atomicAdd(&A[4*c.z + 2], p2);
        atomicAdd(&A[4*c.w + 2], p3);
        atomicAdd(&A[4*r.x + 3], d0);
        atomicAdd(&A[4*r.y + 3], d1);
        atomicAdd(&A[4*r.z + 3], d2);
        atomicAdd(&A[4*r.w + 3], d3);
    } else {
        for (int e = e0; e < E; ++e) {
            int r = row[e], c = col[e];
            float p = A[4*r + 0];
            float d = A[4*c + 1];
            atomicAdd(&A[4*c + 2], p);
            atomicAdd(&A[4*r + 3], d);
        }
    }
}

// t[f] = sum_i w[i]*relu(s[i]*W1[f]+b1[f]);  blockDim.x == HID
__global__ void k_reduce(const float* __restrict__ W1, const float* __restrict__ b1, int n) {
    float* t = g_deg_t + NMAX;
    __shared__ float2 sh[HID];   // {s, w}
    int f = threadIdx.x;
    float W1f = W1[f];
    float b1f = b1[f];
    float acc0 = 0.f, acc1 = 0.f, acc2 = 0.f, acc3 = 0.f;
    for (int base = blockIdx.x * HID; base < n; base += gridDim.x * HID) {
        int tile = n - base;
        if (tile > HID) tile = HID;
        if (f < tile) {
            float4 a = g_A[base + f];            // {p, d, u, v}
            sh[f] = make_float2(a.y * (a.x + a.z), a.y * (a.y + a.w));
        }
        __syncthreads();
        int j = 0;
        for (; j + 3 < tile; j += 4) {
            float2 a = sh[j + 0];
            float2 b = sh[j + 1];
            float2 c = sh[j + 2];
            float2 d = sh[j + 3];
            acc0 += a.y * fmaxf(fmaf(a.x, W1f, b1f), 0.0f);
            acc1 += b.y * fmaxf(fmaf(b.x, W1f, b1f), 0.0f);
            acc2 += c.y * fmaxf(fmaf(c.x, W1f, b1f), 0.0f);
            acc3 += d.y * fmaxf(fmaf(d.x, W1f, b1f), 0.0f);
        }
        for (; j < tile; ++j) {
            float2 a = sh[j];
            acc0 += a.y * fmaxf(fmaf(a.x, W1f, b1f), 0.0f);
        }
        __syncthreads();
    }
    atomicAdd(&t[f], (acc0 + acc1) + (acc2 + acc3));
}

__global__ void k_out(const float* __restrict__ W2, const float* __restrict__ b2,
                      float* __restrict__ out, int n, int odim) {
    const float* t = g_deg_t + NMAX;
    __shared__ float sh_t[HID];
    if (threadIdx.x < HID) sh_t[threadIdx.x] = t[threadIdx.x];
    __syncthreads();
    int k = threadIdx.x;
    if (k < odim) {
        float acc = 0.0f;
        #pragma unroll 16
        for (int f = 0; f < HID; ++f)
            acc = fmaf(sh_t[f], W2[f * odim + k], acc);
        out[k] = acc * (1.0f / (float)n) + b2[k];
    }
}

extern "C" void kernel_launch(void* const* d_in, const int* in_sizes, int n_in,
                              void* d_out, int out_size) {
    const float* x   = (const float*)d_in[0];
    const int*   ei  = (const int*)  d_in[1];
    const float* W1  = (const float*)d_in[2];
    const float* b1  = (const float*)d_in[3];
    const float* W2  = (const float*)d_in[4];
    const float* b2  = (const float*)d_in[5];
    float*       out = (float*)d_out;

    int n = in_sizes[0];
    int E = in_sizes[1] / 2;
    const int* row = ei;
    const int* col = ei + E;
    int odim = out_size;

    void* dp = nullptr;
    cudaGetSymbolAddress(&dp, g_deg_t);
    cudaMemsetAsync(dp, 0, (NMAX + HID) * sizeof(float), 0);

    int tb = 256;
    int e4 = (E + 3) / 4;
    k_deg   <<<(e4 + tb - 1) / tb, tb>>>(col, E);
    k_dinv  <<<(n + tb - 1) / tb, tb>>>(x, n);
    k_edge  <<<(e4 + tb - 1) / tb, tb>>>(row, col, E);
    k_reduce<<<512, HID>>>(W1, b1, n);
    k_out   <<<1, 512>>>(W2, b2, out, n, odim);
}